// round 4
// baseline (speedup 1.0000x reference)
#include <cuda_runtime.h>
#include <cuda_bf16.h>
#include <cstddef>

// Problem constants (fixed-shape problem)
#define BB 512      // batch
#define TT 128      // encoder sequence length
#define II 64       // input dim
#define HH 512      // hidden dim
#define OO 64       // output dim
#define LMAX 300    // max predict length

// Tiling
#define BM 64
#define BN 32
#define BK 32
#define NTHREADS 256

// -------- device scratch (no allocations allowed) --------
__device__ float g_h[2][BB * HH];                 // encoder ping-pong hidden
__device__ float g_hist[(size_t)LMAX * BB * HH];  // decoder hidden history (~315 MB)
__device__ float g_Wdec[4 * HH * HH];             // [r:Whh+Weff | z:Whh+Weff | inn:Weff_n | hn:Whh_n]
__device__ float g_bdec[4 * HH];

__device__ __forceinline__ float sigmoidf_(float x) {
    return 1.0f / (1.0f + __expf(-x));
}

// ---------------------------------------------------------------------------
// zero the initial hidden state
__global__ void k_zero_h0() {
    int i = blockIdx.x * blockDim.x + threadIdx.x;
    if (i < BB * HH) g_h[0][i] = 0.0f;
}

// ---------------------------------------------------------------------------
// Build decoder weights:
//   Weff = Wih @ Wo  ([3H,64] x [64,H])
//   rows [0,2H):  Whh[row] + Weff[row]              (r,z combined)
//   rows [2H,3H): Weff[row]                         (inn)
//   rows [3H,4H): Whh[row-H]                        (hn, i.e. Whh n-rows)
__global__ void k_prep_wdec(const float* __restrict__ Whh,
                            const float* __restrict__ Wih,
                            const float* __restrict__ Wo) {
    int idx = blockIdx.x * blockDim.x + threadIdx.x;   // over 4H*H
    if (idx >= 4 * HH * HH) return;
    int row = idx / HH;
    int k   = idx % HH;
    float val;
    if (row < 3 * HH) {
        float s = 0.0f;
        const float* wr = Wih + (size_t)row * II;
        #pragma unroll 8
        for (int o = 0; o < II; ++o) s += wr[o] * Wo[(size_t)o * HH + k];
        val = (row < 2 * HH) ? (Whh[(size_t)row * HH + k] + s) : s;
    } else {
        val = Whh[(size_t)(row - HH) * HH + k];  // Whh row 2H + (row-3H)
    }
    g_Wdec[idx] = val;
}

// Decoder biases:
//   [0,2H):  bih + bhh + Wih@bo      (r,z)
//   [2H,3H): bih + Wih@bo            (inn)
//   [3H,4H): bhh[row-H]              (hn)
__global__ void k_prep_bdec(const float* __restrict__ bih,
                            const float* __restrict__ bhh,
                            const float* __restrict__ Wih,
                            const float* __restrict__ bo) {
    int idx = blockIdx.x * blockDim.x + threadIdx.x;
    if (idx >= 4 * HH) return;
    float val;
    if (idx < 3 * HH) {
        float s = 0.0f;
        const float* wr = Wih + (size_t)idx * II;
        #pragma unroll 8
        for (int o = 0; o < II; ++o) s += wr[o] * bo[o];
        val = bih[idx] + s + ((idx < 2 * HH) ? bhh[idx] : 0.0f);
    } else {
        val = bhh[idx - HH];
    }
    g_bdec[idx] = val;
}

// ---------------------------------------------------------------------------
// Encoder step: h' = GRU(h, x_t).
// Accumulators: r (K=512+64), z (K=512+64), inn (K=64 from x), hn (K=512 from h)
__global__ __launch_bounds__(NTHREADS) void k_enc_step(
    int t,
    const float* __restrict__ input,   // [B, T, I]
    const float* __restrict__ Whh,     // [3H, H]
    const float* __restrict__ Wih,     // [3H, I]
    const float* __restrict__ bih,
    const float* __restrict__ bhh) {

    const float* hin = g_h[t & 1];
    float* hout = (t == TT - 1) ? g_hist : g_h[(t + 1) & 1];
    const float* x = input + (size_t)t * II;   // row stride T*I

    __shared__ float As[BM][BK + 1];
    __shared__ float Bs[3][BN][BK + 1];

    const int b0 = blockIdx.x * BM;
    const int j0 = blockIdx.y * BN;
    const int tid = threadIdx.x;
    const int tx = tid & 15, ty = tid >> 4;

    float ar[4][2] = {}, az[4][2] = {}, ah[4][2] = {}, an[4][2] = {};

    // ---- main K=512: h vs Whh rows (r,z,n) ----
    for (int k0 = 0; k0 < HH; k0 += BK) {
        #pragma unroll
        for (int u = 0; u < 2; ++u) {
            int f = tid + u * 256; int r = f >> 3; int c = (f & 7) * 4;
            float4 v = *reinterpret_cast<const float4*>(&hin[(size_t)(b0 + r) * HH + k0 + c]);
            As[r][c] = v.x; As[r][c + 1] = v.y; As[r][c + 2] = v.z; As[r][c + 3] = v.w;
        }
        #pragma unroll
        for (int u = 0; u < 3; ++u) {
            int f = tid + u * 256; int g = f >> 8; int rem = f & 255;
            int n = rem >> 3; int c = (rem & 7) * 4;
            float4 v = *reinterpret_cast<const float4*>(
                &Whh[(size_t)(g * HH + j0 + n) * HH + k0 + c]);
            Bs[g][n][c] = v.x; Bs[g][n][c + 1] = v.y; Bs[g][n][c + 2] = v.z; Bs[g][n][c + 3] = v.w;
        }
        __syncthreads();
        #pragma unroll 8
        for (int kk = 0; kk < BK; ++kk) {
            float a0 = As[ty][kk], a1 = As[ty + 16][kk], a2 = As[ty + 32][kk], a3 = As[ty + 48][kk];
            #pragma unroll
            for (int jn = 0; jn < 2; ++jn) {
                int n = tx + 16 * jn;
                float br = Bs[0][n][kk], bz = Bs[1][n][kk], bn = Bs[2][n][kk];
                ar[0][jn] += a0 * br; ar[1][jn] += a1 * br; ar[2][jn] += a2 * br; ar[3][jn] += a3 * br;
                az[0][jn] += a0 * bz; az[1][jn] += a1 * bz; az[2][jn] += a2 * bz; az[3][jn] += a3 * bz;
                ah[0][jn] += a0 * bn; ah[1][jn] += a1 * bn; ah[2][jn] += a2 * bn; ah[3][jn] += a3 * bn;
            }
        }
        __syncthreads();
    }

    // ---- tail K=64: x vs Wih rows (r,z,n) — n goes into 'an' (inn) ----
    for (int k0 = 0; k0 < II; k0 += BK) {
        #pragma unroll
        for (int u = 0; u < 2; ++u) {
            int f = tid + u * 256; int r = f >> 3; int c = (f & 7) * 4;
            float4 v = *reinterpret_cast<const float4*>(
                &x[(size_t)(b0 + r) * (TT * II) + k0 + c]);
            As[r][c] = v.x; As[r][c + 1] = v.y; As[r][c + 2] = v.z; As[r][c + 3] = v.w;
        }
        #pragma unroll
        for (int u = 0; u < 3; ++u) {
            int f = tid + u * 256; int g = f >> 8; int rem = f & 255;
            int n = rem >> 3; int c = (rem & 7) * 4;
            float4 v = *reinterpret_cast<const float4*>(
                &Wih[(size_t)(g * HH + j0 + n) * II + k0 + c]);
            Bs[g][n][c] = v.x; Bs[g][n][c + 1] = v.y; Bs[g][n][c + 2] = v.z; Bs[g][n][c + 3] = v.w;
        }
        __syncthreads();
        #pragma unroll 8
        for (int kk = 0; kk < BK; ++kk) {
            float a0 = As[ty][kk], a1 = As[ty + 16][kk], a2 = As[ty + 32][kk], a3 = As[ty + 48][kk];
            #pragma unroll
            for (int jn = 0; jn < 2; ++jn) {
                int n = tx + 16 * jn;
                float br = Bs[0][n][kk], bz = Bs[1][n][kk], bn = Bs[2][n][kk];
                ar[0][jn] += a0 * br; ar[1][jn] += a1 * br; ar[2][jn] += a2 * br; ar[3][jn] += a3 * br;
                az[0][jn] += a0 * bz; az[1][jn] += a1 * bz; az[2][jn] += a2 * bz; az[3][jn] += a3 * bz;
                an[0][jn] += a0 * bn; an[1][jn] += a1 * bn; an[2][jn] += a2 * bn; an[3][jn] += a3 * bn;
            }
        }
        __syncthreads();
    }

    // ---- epilogue ----
    #pragma unroll
    for (int i = 0; i < 4; ++i) {
        #pragma unroll
        for (int jn = 0; jn < 2; ++jn) {
            int m = b0 + ty + 16 * i;
            int j = j0 + tx + 16 * jn;
            float r = sigmoidf_(ar[i][jn] + bih[j] + bhh[j]);
            float z = sigmoidf_(az[i][jn] + bih[HH + j] + bhh[HH + j]);
            float n = tanhf(an[i][jn] + bih[2 * HH + j] + r * (ah[i][jn] + bhh[2 * HH + j]));
            float hp = hin[(size_t)m * HH + j];
            hout[(size_t)m * HH + j] = (1.0f - z) * n + z * hp;
        }
    }
}

// ---------------------------------------------------------------------------
// Decoder step: h_{t+1} = GRU(h_t, proj(h_t)) folded into 4 dot-groups over K=512.
__global__ __launch_bounds__(NTHREADS) void k_dec_step(int t) {
    const float* hin = g_hist + (size_t)t * BB * HH;
    float* hout = g_hist + (size_t)(t + 1) * BB * HH;

    __shared__ float As[BM][BK + 1];
    __shared__ float Bs[4][BN][BK + 1];

    const int b0 = blockIdx.x * BM;
    const int j0 = blockIdx.y * BN;
    const int tid = threadIdx.x;
    const int tx = tid & 15, ty = tid >> 4;

    float a0v[4][2] = {}, a1v[4][2] = {}, a2v[4][2] = {}, a3v[4][2] = {};

    for (int k0 = 0; k0 < HH; k0 += BK) {
        #pragma unroll
        for (int u = 0; u < 2; ++u) {
            int f = tid + u * 256; int r = f >> 3; int c = (f & 7) * 4;
            float4 v = *reinterpret_cast<const float4*>(&hin[(size_t)(b0 + r) * HH + k0 + c]);
            As[r][c] = v.x; As[r][c + 1] = v.y; As[r][c + 2] = v.z; As[r][c + 3] = v.w;
        }
        #pragma unroll
        for (int u = 0; u < 4; ++u) {
            int f = tid + u * 256; int g = f >> 8; int rem = f & 255;
            int n = rem >> 3; int c = (rem & 7) * 4;
            float4 v = *reinterpret_cast<const float4*>(
                &g_Wdec[(size_t)(g * HH + j0 + n) * HH + k0 + c]);
            Bs[g][n][c] = v.x; Bs[g][n][c + 1] = v.y; Bs[g][n][c + 2] = v.z; Bs[g][n][c + 3] = v.w;
        }
        __syncthreads();
        #pragma unroll 8
        for (int kk = 0; kk < BK; ++kk) {
            float a0 = As[ty][kk], a1 = As[ty + 16][kk], a2 = As[ty + 32][kk], a3 = As[ty + 48][kk];
            #pragma unroll
            for (int jn = 0; jn < 2; ++jn) {
                int n = tx + 16 * jn;
                float b0r = Bs[0][n][kk], b1z = Bs[1][n][kk], b2i = Bs[2][n][kk], b3h = Bs[3][n][kk];
                a0v[0][jn] += a0 * b0r; a0v[1][jn] += a1 * b0r; a0v[2][jn] += a2 * b0r; a0v[3][jn] += a3 * b0r;
                a1v[0][jn] += a0 * b1z; a1v[1][jn] += a1 * b1z; a1v[2][jn] += a2 * b1z; a1v[3][jn] += a3 * b1z;
                a2v[0][jn] += a0 * b2i; a2v[1][jn] += a1 * b2i; a2v[2][jn] += a2 * b2i; a2v[3][jn] += a3 * b2i;
                a3v[0][jn] += a0 * b3h; a3v[1][jn] += a1 * b3h; a3v[2][jn] += a2 * b3h; a3v[3][jn] += a3 * b3h;
            }
        }
        __syncthreads();
    }

    #pragma unroll
    for (int i = 0; i < 4; ++i) {
        #pragma unroll
        for (int jn = 0; jn < 2; ++jn) {
            int m = b0 + ty + 16 * i;
            int j = j0 + tx + 16 * jn;
            float r = sigmoidf_(a0v[i][jn] + g_bdec[j]);
            float z = sigmoidf_(a1v[i][jn] + g_bdec[HH + j]);
            float n = tanhf(a2v[i][jn] + g_bdec[2 * HH + j] + r * (a3v[i][jn] + g_bdec[3 * HH + j]));
            float hp = hin[(size_t)m * HH + j];
            hout[(size_t)m * HH + j] = (1.0f - z) * n + z * hp;
        }
    }
}

// ---------------------------------------------------------------------------
// Final projection: Y[b][t][o] = hist[t][b][:] . Wo[o][:] + bo[o]
__global__ __launch_bounds__(NTHREADS) void k_proj(
    float* __restrict__ out, int L,
    const float* __restrict__ Wo, const float* __restrict__ bo) {

    __shared__ float As[64][BK + 1];
    __shared__ float Bs[64][BK + 1];

    const int row0 = blockIdx.x * 64;
    const int tid = threadIdx.x;
    const int tx = tid & 15, ty = tid >> 4;

    float acc[4][4] = {};

    for (int k0 = 0; k0 < HH; k0 += BK) {
        #pragma unroll
        for (int u = 0; u < 2; ++u) {
            int f = tid + u * 256; int r = f >> 3; int c = (f & 7) * 4;
            float4 v = *reinterpret_cast<const float4*>(
                &g_hist[(size_t)(row0 + r) * HH + k0 + c]);
            As[r][c] = v.x; As[r][c + 1] = v.y; As[r][c + 2] = v.z; As[r][c + 3] = v.w;
        }
        #pragma unroll
        for (int u = 0; u < 2; ++u) {
            int f = tid + u * 256; int r = f >> 3; int c = (f & 7) * 4;
            float4 v = *reinterpret_cast<const float4*>(&Wo[(size_t)r * HH + k0 + c]);
            Bs[r][c] = v.x; Bs[r][c + 1] = v.y; Bs[r][c + 2] = v.z; Bs[r][c + 3] = v.w;
        }
        __syncthreads();
        #pragma unroll 8
        for (int kk = 0; kk < BK; ++kk) {
            float a[4], b[4];
            #pragma unroll
            for (int i = 0; i < 4; ++i) a[i] = As[ty + 16 * i][kk];
            #pragma unroll
            for (int jn = 0; jn < 4; ++jn) b[jn] = Bs[tx + 16 * jn][kk];
            #pragma unroll
            for (int i = 0; i < 4; ++i)
                #pragma unroll
                for (int jn = 0; jn < 4; ++jn)
                    acc[i][jn] += a[i] * b[jn];
        }
        __syncthreads();
    }

    #pragma unroll
    for (int i = 0; i < 4; ++i) {
        int row = row0 + ty + 16 * i;
        int t = row >> 9;          // row / B  (B=512)
        int b = row & (BB - 1);    // row % B
        #pragma unroll
        for (int jn = 0; jn < 4; ++jn) {
            int o = tx + 16 * jn;
            out[((size_t)b * L + t) * OO + o] = acc[i][jn] + bo[o];
        }
    }
}

// ---------------------------------------------------------------------------
extern "C" void kernel_launch(void* const* d_in, const int* in_sizes, int n_in,
                              void* d_out, int out_size) {
    (void)n_in; (void)in_sizes;
    const float* input = (const float*)d_in[0];
    const float* Wih   = (const float*)d_in[1];
    const float* Whh   = (const float*)d_in[2];
    const float* bih   = (const float*)d_in[3];
    const float* bhh   = (const float*)d_in[4];
    const float* Wo    = (const float*)d_in[5];
    const float* bo    = (const float*)d_in[6];
    float* out = (float*)d_out;

    int L = out_size / (BB * OO);
    if (L > LMAX) L = LMAX;
    if (L < 1) L = 1;

    // init + weight prep
    k_zero_h0<<<(BB * HH + 255) / 256, 256>>>();
    k_prep_wdec<<<(4 * HH * HH + 255) / 256, 256>>>(Whh, Wih, Wo);
    k_prep_bdec<<<(4 * HH + 255) / 256, 256>>>(bih, bhh, Wih, bo);

    dim3 grid(BB / BM, HH / BN);   // 8 x 16 = 128 blocks

    // encoder: 128 sequential steps; final writes g_hist[0]
    for (int t = 0; t < TT; ++t)
        k_enc_step<<<grid, NTHREADS>>>(t, input, Whh, Wih, bih, bhh);

    // decoder: L-1 sequential steps, hist[t] -> hist[t+1]
    for (int t = 0; t < L - 1; ++t)
        k_dec_step<<<grid, NTHREADS>>>(t);

    // all projections in one GEMM
    k_proj<<<L * (BB / 64), NTHREADS>>>(out, L, Wo, bo);
}

// round 12
// speedup vs baseline: 1.4809x; 1.4809x over previous
#include <cuda_runtime.h>
#include <cstdint>
#include <cstddef>

// ---------------- problem constants ----------------
#define BB 512
#define TT 128
#define II 64
#define HH 512
#define OO 64
#define LMAX 300
#define KENC 576   // [h(512) | x(64)]
#define KDEC 512

// ---------------- device scratch ----------------
__device__ float g_h[2][BB * HH];
__device__ float g_hist[(size_t)LMAX * BB * HH];   // ~315 MB
__device__ float g_Wdec[4 * HH * KDEC];            // gate-major rows (g*H + j), K cols
__device__ float g_Wenc[4 * HH * KENC];
__device__ float g_bdec[4 * HH];
__device__ float g_benc[4 * HH];

// ---------------- helpers ----------------
__device__ __forceinline__ float tf32r(float x) {
    uint32_t o, i = __float_as_uint(x);
    asm("cvt.rna.tf32.f32 %0, %1;" : "=r"(o) : "r"(i));
    return __uint_as_float(o);
}
__device__ __forceinline__ float sigmoidf_(float x) { return 1.0f / (1.0f + __expf(-x)); }

// mma.sync m16n8k8 tf32: D += A*B  (A row-major 16x8, B col-major 8x8, fp32 accum)
__device__ __forceinline__ void mma8(float d[4], uint32_t a0, uint32_t a1, uint32_t a2,
                                     uint32_t a3, uint32_t b0, uint32_t b1) {
    asm volatile(
        "mma.sync.aligned.m16n8k8.row.col.f32.tf32.tf32.f32 "
        "{%0,%1,%2,%3},{%4,%5,%6,%7},{%8,%9},{%0,%1,%2,%3};"
        : "+f"(d[0]), "+f"(d[1]), "+f"(d[2]), "+f"(d[3])
        : "r"(a0), "r"(a1), "r"(a2), "r"(a3), "r"(b0), "r"(b1));
}

// ---------------- prep kernels ----------------
__global__ void k_zero_h0() {
    int i = blockIdx.x * blockDim.x + threadIdx.x;
    if (i < BB * HH) g_h[0][i] = 0.0f;
}

// decoder weights: fold Wo feedback. gate-major rows (g*H + j), K = 512
//  g0 (r): Whh_r + Wih_r@Wo ; g1 (z): Whh_z + Wih_z@Wo ; g2 (inn): Wih_n@Wo ; g3 (hn): Whh_n
__global__ void k_prep_dec(const float* __restrict__ Whh, const float* __restrict__ Wih,
                           const float* __restrict__ Wo) {
    int idx = blockIdx.x * blockDim.x + threadIdx.x;
    if (idx >= 4 * HH * KDEC) return;
    int row = idx / KDEC;
    int k = idx % KDEC;
    float val;
    if (row < 3 * HH) {
        float s = 0.0f;
        const float* wr = Wih + (size_t)row * II;
        #pragma unroll 8
        for (int o = 0; o < II; ++o) s += wr[o] * Wo[(size_t)o * HH + k];
        val = (row < 2 * HH) ? (Whh[(size_t)row * HH + k] + s) : s;
    } else {
        val = Whh[(size_t)(row - HH) * HH + k];   // Whh n-rows
    }
    g_Wdec[idx] = val;
}

// encoder weights: K = [h(512) | x(64)], zero-padded per gate
__global__ void k_prep_enc(const float* __restrict__ Whh, const float* __restrict__ Wih) {
    int idx = blockIdx.x * blockDim.x + threadIdx.x;
    if (idx >= 4 * HH * KENC) return;
    int row = idx / KENC;
    int k = idx % KENC;
    int g = row >> 9, j = row & (HH - 1);
    float val = 0.0f;
    if (g == 0) val = (k < HH) ? Whh[(size_t)j * HH + k]            : Wih[(size_t)j * II + (k - HH)];
    if (g == 1) val = (k < HH) ? Whh[(size_t)(HH + j) * HH + k]     : Wih[(size_t)(HH + j) * II + (k - HH)];
    if (g == 2) val = (k < HH) ? 0.0f                               : Wih[(size_t)(2 * HH + j) * II + (k - HH)];
    if (g == 3) val = (k < HH) ? Whh[(size_t)(2 * HH + j) * HH + k] : 0.0f;
    g_Wenc[idx] = val;
}

__global__ void k_prep_bias(const float* __restrict__ bih, const float* __restrict__ bhh,
                            const float* __restrict__ Wih, const float* __restrict__ bo) {
    int idx = blockIdx.x * blockDim.x + threadIdx.x;
    if (idx >= 4 * HH) return;
    int g = idx >> 9, j = idx & (HH - 1);
    float be;
    if (g == 0) be = bih[j] + bhh[j];
    else if (g == 1) be = bih[HH + j] + bhh[HH + j];
    else if (g == 2) be = bih[2 * HH + j];
    else be = bhh[2 * HH + j];
    g_benc[idx] = be;
    float bd;
    if (g < 3) {
        int r = g * HH + j;
        float s = 0.0f;
        const float* wr = Wih + (size_t)r * II;
        #pragma unroll 8
        for (int o = 0; o < II; ++o) s += wr[o] * bo[o];
        bd = bih[r] + s + ((g < 2) ? bhh[r] : 0.0f);
    } else {
        bd = bhh[2 * HH + j];
    }
    g_bdec[idx] = bd;
}

// ---------------- fused GRU step: mma.sync 3xTF32 + register epilogue ----------------
// grid (8, 16): CTA tile = 64 batch x (4 gates x 32 j). 8 warps = 2 m-groups x 4 j-blocks.
// Warp tile: 32 m x 8 j x 4 gates (the 4 n-tiles ARE the 4 gates at the same j-range).
#define STEP_THREADS 256

__global__ __launch_bounds__(STEP_THREADS) void k_step(int mode, int t,
                                                       const float* __restrict__ xin) {
    const float* hin;
    float* hout;
    const float* W;
    const float* bias;
    int Kdim;
    if (mode == 0) {
        hin = g_h[t & 1];
        hout = (t == TT - 1) ? g_hist : g_h[(t + 1) & 1];
        W = g_Wenc; bias = g_benc; Kdim = KENC;
    } else {
        hin = g_hist + (size_t)t * BB * HH;
        hout = g_hist + (size_t)(t + 1) * BB * HH;
        W = g_Wdec; bias = g_bdec; Kdim = KDEC;
    }
    const int NC = Kdim / 32;

    __shared__ __align__(16) float As[64][36];    // batch rows x k (stride 36: frag LDS conflict-free)
    __shared__ __align__(16) float Bs[128][36];   // n rows (4g x 32j) x k

    const int tid = threadIdx.x, lane = tid & 31, wid = tid >> 5;
    const int wm = wid >> 2, jb = wid & 3;
    const int m0 = blockIdx.x * 64, j0 = blockIdx.y * 32;
    const int lr = lane >> 2, lc = lane & 3;

    float acc[2][4][4];
    #pragma unroll
    for (int a = 0; a < 2; ++a)
        #pragma unroll
        for (int b = 0; b < 4; ++b)
            #pragma unroll
            for (int q = 0; q < 4; ++q) acc[a][b][q] = 0.0f;

    for (int c = 0; c < NC; ++c) {
        const int kbase = c * 32;
        // ---- stage A (64x32 fp32) ----
        #pragma unroll
        for (int u = 0; u < 2; ++u) {
            int f = tid + u * 256;
            int r = f >> 3, c4 = (f & 7) * 4;
            int kg = kbase + c4;
            const float* src = (kg < HH)
                ? &hin[(size_t)(m0 + r) * HH + kg]
                : &xin[(size_t)(m0 + r) * (TT * II) + t * II + (kg - HH)];
            *reinterpret_cast<float4*>(&As[r][c4]) = *reinterpret_cast<const float4*>(src);
        }
        // ---- stage B (128x32 fp32, gate-packed rows) ----
        #pragma unroll
        for (int u = 0; u < 4; ++u) {
            int f = tid + u * 256;
            int n = f >> 3, c4 = (f & 7) * 4;
            size_t row = (size_t)((n >> 5) * HH + j0 + (n & 31));
            *reinterpret_cast<float4*>(&Bs[n][c4]) =
                *reinterpret_cast<const float4*>(&W[row * Kdim + kbase + c4]);
        }
        __syncthreads();

        #pragma unroll
        for (int ks = 0; ks < 4; ++ks) {
            const int k = ks * 8;
            uint32_t ahi[2][4], alo[2][4], bhi[4][2], blo[4][2];
            #pragma unroll
            for (int mt = 0; mt < 2; ++mt) {
                int ar = wm * 32 + mt * 16 + lr, ac = k + lc;
                float f0 = As[ar][ac], f1 = As[ar + 8][ac];
                float f2 = As[ar][ac + 4], f3 = As[ar + 8][ac + 4];
                float h0 = tf32r(f0), h1 = tf32r(f1), h2 = tf32r(f2), h3 = tf32r(f3);
                ahi[mt][0] = __float_as_uint(h0); alo[mt][0] = __float_as_uint(f0 - h0);
                ahi[mt][1] = __float_as_uint(h1); alo[mt][1] = __float_as_uint(f1 - h1);
                ahi[mt][2] = __float_as_uint(h2); alo[mt][2] = __float_as_uint(f2 - h2);
                ahi[mt][3] = __float_as_uint(h3); alo[mt][3] = __float_as_uint(f3 - h3);
            }
            #pragma unroll
            for (int g = 0; g < 4; ++g) {
                int bn = g * 32 + jb * 8 + lr, bc = k + lc;
                float f0 = Bs[bn][bc], f1 = Bs[bn][bc + 4];
                float h0 = tf32r(f0), h1 = tf32r(f1);
                bhi[g][0] = __float_as_uint(h0); blo[g][0] = __float_as_uint(f0 - h0);
                bhi[g][1] = __float_as_uint(h1); blo[g][1] = __float_as_uint(f1 - h1);
            }
            #pragma unroll
            for (int mt = 0; mt < 2; ++mt)
                #pragma unroll
                for (int g = 0; g < 4; ++g) {
                    mma8(acc[mt][g], ahi[mt][0], ahi[mt][1], ahi[mt][2], ahi[mt][3],
                         bhi[g][0], bhi[g][1]);
                    mma8(acc[mt][g], alo[mt][0], alo[mt][1], alo[mt][2], alo[mt][3],
                         bhi[g][0], bhi[g][1]);
                    mma8(acc[mt][g], ahi[mt][0], ahi[mt][1], ahi[mt][2], ahi[mt][3],
                         blo[g][0], blo[g][1]);
                }
        }
        __syncthreads();
    }

    // ---- GRU epilogue (all 4 gates in registers) ----
    #pragma unroll
    for (int mt = 0; mt < 2; ++mt) {
        #pragma unroll
        for (int half = 0; half < 2; ++half) {
            int m = m0 + wm * 32 + mt * 16 + lr + half * 8;
            int j = j0 + jb * 8 + 2 * lc;                 // even; covers j, j+1
            float2 br = *reinterpret_cast<const float2*>(&bias[j]);
            float2 bz = *reinterpret_cast<const float2*>(&bias[HH + j]);
            float2 bi = *reinterpret_cast<const float2*>(&bias[2 * HH + j]);
            float2 bh = *reinterpret_cast<const float2*>(&bias[3 * HH + j]);
            float2 hp = *reinterpret_cast<const float2*>(&hin[(size_t)m * HH + j]);
            int i0 = half * 2, i1 = half * 2 + 1;
            float r0 = sigmoidf_(acc[mt][0][i0] + br.x);
            float r1 = sigmoidf_(acc[mt][0][i1] + br.y);
            float z0 = sigmoidf_(acc[mt][1][i0] + bz.x);
            float z1 = sigmoidf_(acc[mt][1][i1] + bz.y);
            float n0 = tanhf(acc[mt][2][i0] + bi.x + r0 * (acc[mt][3][i0] + bh.x));
            float n1 = tanhf(acc[mt][2][i1] + bi.y + r1 * (acc[mt][3][i1] + bh.y));
            float2 o;
            o.x = (1.0f - z0) * n0 + z0 * hp.x;
            o.y = (1.0f - z1) * n1 + z1 * hp.y;
            *reinterpret_cast<float2*>(&hout[(size_t)m * HH + j]) = o;
        }
    }
}

// ---------------- final projection (SIMT, one launch) ----------------
#define PBK 32
__global__ __launch_bounds__(256) void k_proj(float* __restrict__ out, int L,
                                              const float* __restrict__ Wo,
                                              const float* __restrict__ bo) {
    __shared__ float As[64][PBK + 1];
    __shared__ float Bs[64][PBK + 1];
    const int row0 = blockIdx.x * 64;
    const int tid = threadIdx.x;
    const int tx = tid & 15, ty = tid >> 4;
    float acc[4][4] = {};
    for (int k0 = 0; k0 < HH; k0 += PBK) {
        #pragma unroll
        for (int u = 0; u < 2; ++u) {
            int f = tid + u * 256; int r = f >> 3; int c = (f & 7) * 4;
            float4 v = *reinterpret_cast<const float4*>(&g_hist[(size_t)(row0 + r) * HH + k0 + c]);
            As[r][c] = v.x; As[r][c + 1] = v.y; As[r][c + 2] = v.z; As[r][c + 3] = v.w;
        }
        #pragma unroll
        for (int u = 0; u < 2; ++u) {
            int f = tid + u * 256; int r = f >> 3; int c = (f & 7) * 4;
            float4 v = *reinterpret_cast<const float4*>(&Wo[(size_t)r * HH + k0 + c]);
            Bs[r][c] = v.x; Bs[r][c + 1] = v.y; Bs[r][c + 2] = v.z; Bs[r][c + 3] = v.w;
        }
        __syncthreads();
        #pragma unroll 8
        for (int kk = 0; kk < PBK; ++kk) {
            float a[4], b[4];
            #pragma unroll
            for (int i = 0; i < 4; ++i) a[i] = As[ty + 16 * i][kk];
            #pragma unroll
            for (int jn = 0; jn < 4; ++jn) b[jn] = Bs[tx + 16 * jn][kk];
            #pragma unroll
            for (int i = 0; i < 4; ++i)
                #pragma unroll
                for (int jn = 0; jn < 4; ++jn) acc[i][jn] += a[i] * b[jn];
        }
        __syncthreads();
    }
    #pragma unroll
    for (int i = 0; i < 4; ++i) {
        int row = row0 + ty + 16 * i;
        int tt = row >> 9;
        int b = row & (BB - 1);
        #pragma unroll
        for (int jn = 0; jn < 4; ++jn) {
            int o = tx + 16 * jn;
            out[((size_t)b * L + tt) * OO + o] = acc[i][jn] + bo[o];
        }
    }
}

// ---------------- host launcher ----------------
extern "C" void kernel_launch(void* const* d_in, const int* in_sizes, int n_in,
                              void* d_out, int out_size) {
    (void)n_in; (void)in_sizes;
    const float* input = (const float*)d_in[0];
    const float* Wih   = (const float*)d_in[1];
    const float* Whh   = (const float*)d_in[2];
    const float* bih   = (const float*)d_in[3];
    const float* bhh   = (const float*)d_in[4];
    const float* Wo    = (const float*)d_in[5];
    const float* bo    = (const float*)d_in[6];
    float* out = (float*)d_out;

    int L = out_size / (BB * OO);
    if (L > LMAX) L = LMAX;
    if (L < 1) L = 1;

    k_zero_h0<<<(BB * HH + 255) / 256, 256>>>();
    k_prep_dec<<<(4 * HH * KDEC + 255) / 256, 256>>>(Whh, Wih, Wo);
    k_prep_enc<<<(4 * HH * KENC + 255) / 256, 256>>>(Whh, Wih);
    k_prep_bias<<<(4 * HH + 255) / 256, 256>>>(bih, bhh, Wih, bo);

    dim3 grid(BB / 64, HH / 32);   // (8, 16) = 128 CTAs

    for (int t = 0; t < TT; ++t)
        k_step<<<grid, STEP_THREADS>>>(0, t, input);

    for (int t = 0; t < L - 1; ++t)
        k_step<<<grid, STEP_THREADS>>>(1, t, input);

    k_proj<<<L * (BB / 64), 256>>>(out, L, Wo, bo);
}

// round 13
// speedup vs baseline: 1.8968x; 1.2809x over previous
#include <cuda_runtime.h>
#include <cstdint>
#include <cstddef>

// ---------------- problem constants ----------------
#define BB 512
#define TT 128
#define II 64
#define HH 512
#define OO 64
#define LMAX 300
#define KENC 576   // [h(512) | x(64)]
#define KDEC 512

// ---------------- device scratch ----------------
__device__ float g_h[2][BB * HH];                   // fp32 encoder ping-pong (for hp + handoff)
__device__ float g_hist[(size_t)LMAX * BB * HH];    // fp32 decoder hidden history (~315 MB)
__device__ uint2 g_hs0[BB * HH / 2];                // split-h ping-pong (bf16 hi|lo packed pairs)
__device__ uint2 g_hs1[BB * HH / 2];
__device__ uint2 g_Wdec_s[4 * HH * KDEC / 2];       // presplit weights, u64 per k-pair
__device__ uint2 g_Wenc_s[4 * HH * KENC / 2];
__device__ uint2 g_xs[(size_t)BB * TT * II / 2];    // presplit encoder inputs
__device__ float g_bdec[4 * HH];
__device__ float g_benc[4 * HH];

// ---------------- helpers ----------------
__device__ __forceinline__ float sigmoidf_(float x) { return 1.0f / (1.0f + __expf(-x)); }

// pack (v0, v1) -> {bf16x2 hi, bf16x2 lo}; low half = v0 (even k)
__device__ __forceinline__ uint2 split2(float v0, float v1) {
    uint32_t hi;
    asm("cvt.rn.bf16x2.f32 %0, %1, %2;" : "=r"(hi) : "f"(v1), "f"(v0));
    float h0 = __uint_as_float(hi << 16);
    float h1 = __uint_as_float(hi & 0xFFFF0000u);
    uint32_t lo;
    asm("cvt.rn.bf16x2.f32 %0, %1, %2;" : "=r"(lo) : "f"(v1 - h1), "f"(v0 - h0));
    return make_uint2(hi, lo);
}

// mma.sync m16n8k16 bf16: D += A*B (A row-major 16x16, B col-major 16x8, fp32 accum)
__device__ __forceinline__ void mmab(float d[4], uint32_t a0, uint32_t a1, uint32_t a2,
                                     uint32_t a3, uint32_t b0, uint32_t b1) {
    asm volatile(
        "mma.sync.aligned.m16n8k16.row.col.f32.bf16.bf16.f32 "
        "{%0,%1,%2,%3},{%4,%5,%6,%7},{%8,%9},{%0,%1,%2,%3};"
        : "+f"(d[0]), "+f"(d[1]), "+f"(d[2]), "+f"(d[3])
        : "r"(a0), "r"(a1), "r"(a2), "r"(a3), "r"(b0), "r"(b1));
}

// ---------------- prep kernels ----------------
__global__ void k_zero_h0() {
    int i = blockIdx.x * blockDim.x + threadIdx.x;
    if (i < BB * HH) g_h[0][i] = 0.0f;
    if (i < BB * HH / 2) g_hs0[i] = make_uint2(0u, 0u);
}

// decoder weights (Wo fold), gate-major rows (g*H + j), K=512; split per k-pair
__global__ void k_prep_dec(const float* __restrict__ Whh, const float* __restrict__ Wih,
                           const float* __restrict__ Wo) {
    int idx = blockIdx.x * blockDim.x + threadIdx.x;   // over 4H * K/2
    if (idx >= 4 * HH * (KDEC / 2)) return;
    int row = idx / (KDEC / 2);
    int kp = idx % (KDEC / 2);
    float v[2];
    #pragma unroll
    for (int e = 0; e < 2; ++e) {
        int k = 2 * kp + e;
        if (row < 3 * HH) {
            float s = 0.0f;
            const float* wr = Wih + (size_t)row * II;
            #pragma unroll 8
            for (int o = 0; o < II; ++o) s += wr[o] * Wo[(size_t)o * HH + k];
            v[e] = (row < 2 * HH) ? (Whh[(size_t)row * HH + k] + s) : s;
        } else {
            v[e] = Whh[(size_t)(row - HH) * HH + k];
        }
    }
    g_Wdec_s[idx] = split2(v[0], v[1]);
}

// encoder weights: K = [h(512) | x(64)], zero-padded per gate; split per k-pair
__global__ void k_prep_enc(const float* __restrict__ Whh, const float* __restrict__ Wih) {
    int idx = blockIdx.x * blockDim.x + threadIdx.x;   // over 4H * KENC/2
    if (idx >= 4 * HH * (KENC / 2)) return;
    int row = idx / (KENC / 2);
    int kp = idx % (KENC / 2);
    int g = row >> 9, j = row & (HH - 1);
    float v[2];
    #pragma unroll
    for (int e = 0; e < 2; ++e) {
        int k = 2 * kp + e;
        float val = 0.0f;
        if (g == 0) val = (k < HH) ? Whh[(size_t)j * HH + k]            : Wih[(size_t)j * II + (k - HH)];
        if (g == 1) val = (k < HH) ? Whh[(size_t)(HH + j) * HH + k]     : Wih[(size_t)(HH + j) * II + (k - HH)];
        if (g == 2) val = (k < HH) ? 0.0f                               : Wih[(size_t)(2 * HH + j) * II + (k - HH)];
        if (g == 3) val = (k < HH) ? Whh[(size_t)(2 * HH + j) * HH + k] : 0.0f;
        v[e] = val;
    }
    g_Wenc_s[idx] = split2(v[0], v[1]);
}

// presplit encoder inputs
__global__ void k_prep_x(const float* __restrict__ input) {
    size_t idx = (size_t)blockIdx.x * blockDim.x + threadIdx.x;
    if (idx >= (size_t)BB * TT * II / 2) return;
    g_xs[idx] = split2(input[2 * idx], input[2 * idx + 1]);
}

__global__ void k_prep_bias(const float* __restrict__ bih, const float* __restrict__ bhh,
                            const float* __restrict__ Wih, const float* __restrict__ bo) {
    int idx = blockIdx.x * blockDim.x + threadIdx.x;
    if (idx >= 4 * HH) return;
    int g = idx >> 9, j = idx & (HH - 1);
    float be;
    if (g == 0) be = bih[j] + bhh[j];
    else if (g == 1) be = bih[HH + j] + bhh[HH + j];
    else if (g == 2) be = bih[2 * HH + j];
    else be = bhh[2 * HH + j];
    g_benc[idx] = be;
    float bd;
    if (g < 3) {
        int r = g * HH + j;
        float s = 0.0f;
        const float* wr = Wih + (size_t)r * II;
        #pragma unroll 8
        for (int o = 0; o < II; ++o) s += wr[o] * bo[o];
        bd = bih[r] + s + ((g < 2) ? bhh[r] : 0.0f);
    } else {
        bd = bhh[2 * HH + j];
    }
    g_bdec[idx] = bd;
}

// ---------------- fused GRU step: bf16x3 mma.sync + register epilogue ----------------
// grid (8, 16): CTA tile = 64 batch x (4 gates x 32 j). 8 warps = 2 m-groups x 4 j-blocks.
#define STEP_THREADS 256
#define SPITCH 20   // u64 stride per smem row (frag LDS.64 conflict-free)

__global__ __launch_bounds__(STEP_THREADS) void k_step(int mode, int t) {
    const float* hin;
    float* hout;
    const uint2* hs_in;
    uint2* hs_out;
    const uint2* Ws;
    const float* bias;
    int Kdim;
    if (mode == 0) {
        hin = g_h[t & 1];
        hout = (t == TT - 1) ? g_hist : g_h[(t + 1) & 1];
        hs_in = (t & 1) ? g_hs1 : g_hs0;
        hs_out = (t & 1) ? g_hs0 : g_hs1;
        Ws = g_Wenc_s; bias = g_benc; Kdim = KENC;
    } else {
        hin = g_hist + (size_t)t * BB * HH;
        hout = g_hist + (size_t)(t + 1) * BB * HH;
        hs_in = (t & 1) ? g_hs1 : g_hs0;
        hs_out = (t & 1) ? g_hs0 : g_hs1;
        Ws = g_Wdec_s; bias = g_bdec; Kdim = KDEC;
    }
    const int NC = Kdim / 32;

    __shared__ __align__(16) uint2 As[64][SPITCH];    // batch rows x k-pairs (hi|lo u64)
    __shared__ __align__(16) uint2 Bs[128][SPITCH];   // n rows (4g x 32j) x k-pairs

    const int tid = threadIdx.x, lane = tid & 31, wid = tid >> 5;
    const int wm = wid >> 2, jb = wid & 3;
    const int m0 = blockIdx.x * 64, j0 = blockIdx.y * 32;
    const int lr = lane >> 2, lc = lane & 3;

    float acc[2][4][4];
    #pragma unroll
    for (int a = 0; a < 2; ++a)
        #pragma unroll
        for (int b = 0; b < 4; ++b)
            #pragma unroll
            for (int q = 0; q < 4; ++q) acc[a][b][q] = 0.0f;

    for (int c = 0; c < NC; ++c) {
        const int kp0 = c * 16;   // u64 (k-pair) base of this 32-k chunk
        // ---- stage A: 64 rows x 16 u64 (uint4 = 2 u64 per load) ----
        #pragma unroll
        for (int u = 0; u < 2; ++u) {
            int f = tid + u * 256;
            int r = f >> 3, cp = (f & 7) * 2;
            uint4 v;
            if (kp0 < HH / 2) {
                v = *reinterpret_cast<const uint4*>(&hs_in[(size_t)(m0 + r) * (HH / 2) + kp0 + cp]);
            } else {
                v = *reinterpret_cast<const uint4*>(
                    &g_xs[(size_t)(m0 + r) * (TT * II / 2) + (size_t)t * (II / 2) + (kp0 - HH / 2) + cp]);
            }
            As[r][cp] = make_uint2(v.x, v.y);
            As[r][cp + 1] = make_uint2(v.z, v.w);
        }
        // ---- stage B: 128 rows x 16 u64 ----
        #pragma unroll
        for (int u = 0; u < 4; ++u) {
            int f = tid + u * 256;
            int n = f >> 3, cp = (f & 7) * 2;
            size_t row = (size_t)((n >> 5) * HH + j0 + (n & 31));
            uint4 v = *reinterpret_cast<const uint4*>(&Ws[row * (Kdim / 2) + kp0 + cp]);
            Bs[n][cp] = make_uint2(v.x, v.y);
            Bs[n][cp + 1] = make_uint2(v.z, v.w);
        }
        __syncthreads();

        #pragma unroll
        for (int ks = 0; ks < 2; ++ks) {
            const int ko = ks * 8;   // u64 offset of this k16
            uint2 qa[2][4];
            #pragma unroll
            for (int mt = 0; mt < 2; ++mt) {
                int ar = wm * 32 + mt * 16 + lr;
                qa[mt][0] = As[ar][ko + lc];
                qa[mt][1] = As[ar + 8][ko + lc];
                qa[mt][2] = As[ar][ko + lc + 4];
                qa[mt][3] = As[ar + 8][ko + lc + 4];
            }
            #pragma unroll
            for (int g = 0; g < 4; ++g) {
                int bn = g * 32 + jb * 8 + lr;
                uint2 p0 = Bs[bn][ko + lc];
                uint2 p1 = Bs[bn][ko + lc + 4];
                #pragma unroll
                for (int mt = 0; mt < 2; ++mt) {
                    mmab(acc[mt][g], qa[mt][0].x, qa[mt][1].x, qa[mt][2].x, qa[mt][3].x,
                         p0.x, p1.x);                      // hi*hi
                    mmab(acc[mt][g], qa[mt][0].x, qa[mt][1].x, qa[mt][2].x, qa[mt][3].x,
                         p0.y, p1.y);                      // hi*lo
                    mmab(acc[mt][g], qa[mt][0].y, qa[mt][1].y, qa[mt][2].y, qa[mt][3].y,
                         p0.x, p1.x);                      // lo*hi
                }
            }
        }
        __syncthreads();
    }

    // ---- GRU epilogue (all 4 gates in registers); also emit split-h for next step ----
    #pragma unroll
    for (int mt = 0; mt < 2; ++mt) {
        #pragma unroll
        for (int half = 0; half < 2; ++half) {
            int m = m0 + wm * 32 + mt * 16 + lr + half * 8;
            int j = j0 + jb * 8 + 2 * lc;                 // even; covers j, j+1
            float2 br = *reinterpret_cast<const float2*>(&bias[j]);
            float2 bz = *reinterpret_cast<const float2*>(&bias[HH + j]);
            float2 bi = *reinterpret_cast<const float2*>(&bias[2 * HH + j]);
            float2 bh = *reinterpret_cast<const float2*>(&bias[3 * HH + j]);
            float2 hp = *reinterpret_cast<const float2*>(&hin[(size_t)m * HH + j]);
            int i0 = half * 2, i1 = half * 2 + 1;
            float r0 = sigmoidf_(acc[mt][0][i0] + br.x);
            float r1 = sigmoidf_(acc[mt][0][i1] + br.y);
            float z0 = sigmoidf_(acc[mt][1][i0] + bz.x);
            float z1 = sigmoidf_(acc[mt][1][i1] + bz.y);
            float n0 = tanhf(acc[mt][2][i0] + bi.x + r0 * (acc[mt][3][i0] + bh.x));
            float n1 = tanhf(acc[mt][2][i1] + bi.y + r1 * (acc[mt][3][i1] + bh.y));
            float2 o;
            o.x = (1.0f - z0) * n0 + z0 * hp.x;
            o.y = (1.0f - z1) * n1 + z1 * hp.y;
            *reinterpret_cast<float2*>(&hout[(size_t)m * HH + j]) = o;
            hs_out[(size_t)m * (HH / 2) + (j >> 1)] = split2(o.x, o.y);
        }
    }
}

// ---------------- final projection (SIMT, one launch) ----------------
#define PBK 32
__global__ __launch_bounds__(256) void k_proj(float* __restrict__ out, int L,
                                              const float* __restrict__ Wo,
                                              const float* __restrict__ bo) {
    __shared__ float As[64][PBK + 1];
    __shared__ float Bs[64][PBK + 1];
    const int row0 = blockIdx.x * 64;
    const int tid = threadIdx.x;
    const int tx = tid & 15, ty = tid >> 4;
    float acc[4][4] = {};
    for (int k0 = 0; k0 < HH; k0 += PBK) {
        #pragma unroll
        for (int u = 0; u < 2; ++u) {
            int f = tid + u * 256; int r = f >> 3; int c = (f & 7) * 4;
            float4 v = *reinterpret_cast<const float4*>(&g_hist[(size_t)(row0 + r) * HH + k0 + c]);
            As[r][c] = v.x; As[r][c + 1] = v.y; As[r][c + 2] = v.z; As[r][c + 3] = v.w;
        }
        #pragma unroll
        for (int u = 0; u < 2; ++u) {
            int f = tid + u * 256; int r = f >> 3; int c = (f & 7) * 4;
            float4 v = *reinterpret_cast<const float4*>(&Wo[(size_t)r * HH + k0 + c]);
            Bs[r][c] = v.x; Bs[r][c + 1] = v.y; Bs[r][c + 2] = v.z; Bs[r][c + 3] = v.w;
        }
        __syncthreads();
        #pragma unroll 8
        for (int kk = 0; kk < PBK; ++kk) {
            float a[4], b[4];
            #pragma unroll
            for (int i = 0; i < 4; ++i) a[i] = As[ty + 16 * i][kk];
            #pragma unroll
            for (int jn = 0; jn < 4; ++jn) b[jn] = Bs[tx + 16 * jn][kk];
            #pragma unroll
            for (int i = 0; i < 4; ++i)
                #pragma unroll
                for (int jn = 0; jn < 4; ++jn) acc[i][jn] += a[i] * b[jn];
        }
        __syncthreads();
    }
    #pragma unroll
    for (int i = 0; i < 4; ++i) {
        int row = row0 + ty + 16 * i;
        int tt = row >> 9;
        int b = row & (BB - 1);
        #pragma unroll
        for (int jn = 0; jn < 4; ++jn) {
            int o = tx + 16 * jn;
            out[((size_t)b * L + tt) * OO + o] = acc[i][jn] + bo[o];
        }
    }
}

// ---------------- host launcher ----------------
extern "C" void kernel_launch(void* const* d_in, const int* in_sizes, int n_in,
                              void* d_out, int out_size) {
    (void)n_in; (void)in_sizes;
    const float* input = (const float*)d_in[0];
    const float* Wih   = (const float*)d_in[1];
    const float* Whh   = (const float*)d_in[2];
    const float* bih   = (const float*)d_in[3];
    const float* bhh   = (const float*)d_in[4];
    const float* Wo    = (const float*)d_in[5];
    const float* bo    = (const float*)d_in[6];
    float* out = (float*)d_out;

    int L = out_size / (BB * OO);
    if (L > LMAX) L = LMAX;
    if (L < 1) L = 1;

    k_zero_h0<<<(BB * HH + 255) / 256, 256>>>();
    k_prep_dec<<<(4 * HH * (KDEC / 2) + 255) / 256, 256>>>(Whh, Wih, Wo);
    k_prep_enc<<<(4 * HH * (KENC / 2) + 255) / 256, 256>>>(Whh, Wih);
    k_prep_x<<<(int)(((size_t)BB * TT * II / 2 + 255) / 256), 256>>>(input);
    k_prep_bias<<<(4 * HH + 255) / 256, 256>>>(bih, bhh, Wih, bo);

    dim3 grid(BB / 64, HH / 32);   // (8, 16) = 128 CTAs

    for (int t = 0; t < TT; ++t)
        k_step<<<grid, STEP_THREADS>>>(0, t);

    for (int t = 0; t < L - 1; ++t)
        k_step<<<grid, STEP_THREADS>>>(1, t);

    k_proj<<<L * (BB / 64), 256>>>(out, L, Wo, bo);
}

// round 14
// speedup vs baseline: 2.3075x; 1.2165x over previous
#include <cuda_runtime.h>
#include <cstdint>
#include <cstddef>

// ---------------- problem constants ----------------
#define BB 512
#define TT 128
#define II 64
#define HH 512
#define OO 64
#define LMAX 300
#define KENC 576   // [h(512) | x(64)]
#define KDEC 512

#define NCTA 128   // persistent grid size (8 x 16)

// ---------------- device scratch ----------------
__device__ float g_h[2][BB * HH];                   // fp32 encoder ping-pong
__device__ float g_hist[(size_t)LMAX * BB * HH];    // fp32 decoder hidden history
__device__ uint2 g_hs0[BB * HH / 2];                // split-h ping-pong (bf16 hi|lo pairs)
__device__ uint2 g_hs1[BB * HH / 2];
__device__ uint2 g_Wdec_s[4 * HH * KDEC / 2];
__device__ uint2 g_Wenc_s[4 * HH * KENC / 2];
__device__ uint2 g_xs[(size_t)BB * TT * II / 2];
__device__ float g_bdec[4 * HH];
__device__ float g_benc[4 * HH];
__device__ unsigned g_bar;                          // grid barrier (zeroed every launch)

// ---------------- helpers ----------------
__device__ __forceinline__ float sigmoidf_(float x) { return 1.0f / (1.0f + __expf(-x)); }

__device__ __forceinline__ uint2 split2(float v0, float v1) {
    uint32_t hi;
    asm("cvt.rn.bf16x2.f32 %0, %1, %2;" : "=r"(hi) : "f"(v1), "f"(v0));
    float h0 = __uint_as_float(hi << 16);
    float h1 = __uint_as_float(hi & 0xFFFF0000u);
    uint32_t lo;
    asm("cvt.rn.bf16x2.f32 %0, %1, %2;" : "=r"(lo) : "f"(v1 - h1), "f"(v0 - h0));
    return make_uint2(hi, lo);
}

__device__ __forceinline__ void mmab(float d[4], uint32_t a0, uint32_t a1, uint32_t a2,
                                     uint32_t a3, uint32_t b0, uint32_t b1) {
    asm volatile(
        "mma.sync.aligned.m16n8k16.row.col.f32.bf16.bf16.f32 "
        "{%0,%1,%2,%3},{%4,%5,%6,%7},{%8,%9},{%0,%1,%2,%3};"
        : "+f"(d[0]), "+f"(d[1]), "+f"(d[2]), "+f"(d[3])
        : "r"(a0), "r"(a1), "r"(a2), "r"(a3), "r"(b0), "r"(b1));
}

__device__ __forceinline__ void cp16(uint32_t saddr, const void* gaddr) {
    asm volatile("cp.async.cg.shared.global [%0], [%1], 16;"
                 :: "r"(saddr), "l"(gaddr) : "memory");
}
__device__ __forceinline__ uint32_t smem_u32_(const void* p) {
    uint32_t a;
    asm("{ .reg .u64 t; cvta.to.shared.u64 t, %1; cvt.u32.u64 %0, t; }" : "=r"(a) : "l"(p));
    return a;
}

// ---------------- prep kernels ----------------
__global__ void k_zero_h0() {
    int i = blockIdx.x * blockDim.x + threadIdx.x;
    if (i < BB * HH) g_h[0][i] = 0.0f;
    if (i < BB * HH / 2) g_hs0[i] = make_uint2(0u, 0u);
    if (i == 0) g_bar = 0u;
}

__global__ void k_prep_dec(const float* __restrict__ Whh, const float* __restrict__ Wih,
                           const float* __restrict__ Wo) {
    int idx = blockIdx.x * blockDim.x + threadIdx.x;
    if (idx >= 4 * HH * (KDEC / 2)) return;
    int row = idx / (KDEC / 2);
    int kp = idx % (KDEC / 2);
    float v[2];
    #pragma unroll
    for (int e = 0; e < 2; ++e) {
        int k = 2 * kp + e;
        if (row < 3 * HH) {
            float s = 0.0f;
            const float* wr = Wih + (size_t)row * II;
            #pragma unroll 8
            for (int o = 0; o < II; ++o) s += wr[o] * Wo[(size_t)o * HH + k];
            v[e] = (row < 2 * HH) ? (Whh[(size_t)row * HH + k] + s) : s;
        } else {
            v[e] = Whh[(size_t)(row - HH) * HH + k];
        }
    }
    g_Wdec_s[idx] = split2(v[0], v[1]);
}

__global__ void k_prep_enc(const float* __restrict__ Whh, const float* __restrict__ Wih) {
    int idx = blockIdx.x * blockDim.x + threadIdx.x;
    if (idx >= 4 * HH * (KENC / 2)) return;
    int row = idx / (KENC / 2);
    int kp = idx % (KENC / 2);
    int g = row >> 9, j = row & (HH - 1);
    float v[2];
    #pragma unroll
    for (int e = 0; e < 2; ++e) {
        int k = 2 * kp + e;
        float val = 0.0f;
        if (g == 0) val = (k < HH) ? Whh[(size_t)j * HH + k]            : Wih[(size_t)j * II + (k - HH)];
        if (g == 1) val = (k < HH) ? Whh[(size_t)(HH + j) * HH + k]     : Wih[(size_t)(HH + j) * II + (k - HH)];
        if (g == 2) val = (k < HH) ? 0.0f                               : Wih[(size_t)(2 * HH + j) * II + (k - HH)];
        if (g == 3) val = (k < HH) ? Whh[(size_t)(2 * HH + j) * HH + k] : 0.0f;
        v[e] = val;
    }
    g_Wenc_s[idx] = split2(v[0], v[1]);
}

__global__ void k_prep_x(const float* __restrict__ input) {
    size_t idx = (size_t)blockIdx.x * blockDim.x + threadIdx.x;
    if (idx >= (size_t)BB * TT * II / 2) return;
    g_xs[idx] = split2(input[2 * idx], input[2 * idx + 1]);
}

__global__ void k_prep_bias(const float* __restrict__ bih, const float* __restrict__ bhh,
                            const float* __restrict__ Wih, const float* __restrict__ bo) {
    int idx = blockIdx.x * blockDim.x + threadIdx.x;
    if (idx >= 4 * HH) return;
    int g = idx >> 9, j = idx & (HH - 1);
    float be;
    if (g == 0) be = bih[j] + bhh[j];
    else if (g == 1) be = bih[HH + j] + bhh[HH + j];
    else if (g == 2) be = bih[2 * HH + j];
    else be = bhh[2 * HH + j];
    g_benc[idx] = be;
    float bd;
    if (g < 3) {
        int r = g * HH + j;
        float s = 0.0f;
        const float* wr = Wih + (size_t)r * II;
        #pragma unroll 8
        for (int o = 0; o < II; ++o) s += wr[o] * bo[o];
        bd = bih[r] + s + ((g < 2) ? bhh[r] : 0.0f);
    } else {
        bd = bhh[2 * HH + j];
    }
    g_bdec[idx] = bd;
}

// ---------------- persistent fused GRU: all steps in one kernel ----------------
// grid (8, 16) = 128 CTAs, 1/SM (all resident). CTA tile 64 batch x (4 gates x 32 j).
// 2-stage cp.async pipeline over K-chunks of 32; bf16x3 mma; register GRU epilogue;
// monotone atomic grid barrier between steps.
#define STEP_THREADS 256
#define SPITCH 20                                      // u64 per smem row
#define ROWS_BUF 192                                   // 64 A rows + 128 B rows
#define BUF_U64 (ROWS_BUF * SPITCH)
#define SMEM_BYTES (2 * BUF_U64 * 8)                   // 61440

__global__ __launch_bounds__(STEP_THREADS, 1) void k_gru(int L) {
    extern __shared__ __align__(16) uint2 sm[];        // [2][192][SPITCH]

    const int tid = threadIdx.x, lane = tid & 31, wid = tid >> 5;
    const int wm = wid >> 2, jb = wid & 3;
    const int m0 = blockIdx.x * 64, j0 = blockIdx.y * 32;
    const int lr = lane >> 2, lc = lane & 3;
    const uint32_t sbase = smem_u32_(sm);

    // per-thread staging coords (fixed across chunks)
    const int arow = (tid >> 3);                        // A: rows 0..31 (u=0) / 32..63 (u=1)
    const int acp = (tid & 7) * 2;

    const int total = TT + (L - 1);
    for (int s = 0; s < total; ++s) {
        const int mode = (s < TT) ? 0 : 1;
        const int t = mode ? (s - TT) : s;

        const float* hin;
        float* hout;
        const uint2* hs_in;
        uint2* hs_out;
        const uint2* Ws;
        const float* bias;
        int Kdim;
        if (mode == 0) {
            hin = g_h[t & 1];
            hout = (t == TT - 1) ? g_hist : g_h[(t + 1) & 1];
            hs_in = (t & 1) ? g_hs1 : g_hs0;
            hs_out = (t & 1) ? g_hs0 : g_hs1;
            Ws = g_Wenc_s; bias = g_benc; Kdim = KENC;
        } else {
            hin = g_hist + (size_t)t * BB * HH;
            hout = g_hist + (size_t)(t + 1) * BB * HH;
            hs_in = (t & 1) ? g_hs1 : g_hs0;
            hs_out = (t & 1) ? g_hs0 : g_hs1;
            Ws = g_Wdec_s; bias = g_bdec; Kdim = KDEC;
        }
        const int NC = Kdim / 32;

        float acc[2][4][4];
        #pragma unroll
        for (int a = 0; a < 2; ++a)
            #pragma unroll
            for (int b = 0; b < 4; ++b)
                #pragma unroll
                for (int q = 0; q < 4; ++q) acc[a][b][q] = 0.0f;

        // ---- issue chunk cc into buffer b ----
        auto issue = [&](int cc, int b) {
            const int kp0 = cc * 16;
            const uint32_t bb_ = sbase + (uint32_t)b * (BUF_U64 * 8);
            #pragma unroll
            for (int u = 0; u < 2; ++u) {
                int r = arow + u * 32;
                const void* gp = (kp0 < HH / 2)
                    ? (const void*)&hs_in[(size_t)(m0 + r) * (HH / 2) + kp0 + acp]
                    : (const void*)&g_xs[(size_t)(m0 + r) * (TT * II / 2) + (size_t)t * (II / 2) + (kp0 - HH / 2) + acp];
                cp16(bb_ + (uint32_t)(r * SPITCH + acp) * 8, gp);
            }
            #pragma unroll
            for (int u = 0; u < 4; ++u) {
                int f = tid + u * 256;
                int n = f >> 3, cp = (f & 7) * 2;
                size_t row = (size_t)((n >> 5) * HH + j0 + (n & 31));
                cp16(bb_ + (uint32_t)((64 + n) * SPITCH + cp) * 8,
                     &Ws[row * (Kdim / 2) + kp0 + cp]);
            }
            asm volatile("cp.async.commit_group;" ::: "memory");
        };

        issue(0, 0);
        for (int c = 0; c < NC; ++c) {
            const int b = c & 1;
            if (c + 1 < NC) {
                issue(c + 1, b ^ 1);
                asm volatile("cp.async.wait_group 1;" ::: "memory");
            } else {
                asm volatile("cp.async.wait_group 0;" ::: "memory");
            }
            __syncthreads();

            const uint2* A = sm + (size_t)b * BUF_U64;            // rows 0..63
            const uint2* Bm = A + 64 * SPITCH;                    // rows 0..127
            #pragma unroll
            for (int ks = 0; ks < 2; ++ks) {
                const int ko = ks * 8;
                uint2 qa[2][4];
                #pragma unroll
                for (int mt = 0; mt < 2; ++mt) {
                    int ar = wm * 32 + mt * 16 + lr;
                    qa[mt][0] = A[ar * SPITCH + ko + lc];
                    qa[mt][1] = A[(ar + 8) * SPITCH + ko + lc];
                    qa[mt][2] = A[ar * SPITCH + ko + lc + 4];
                    qa[mt][3] = A[(ar + 8) * SPITCH + ko + lc + 4];
                }
                #pragma unroll
                for (int g = 0; g < 4; ++g) {
                    int bn = g * 32 + jb * 8 + lr;
                    uint2 p0 = Bm[bn * SPITCH + ko + lc];
                    uint2 p1 = Bm[bn * SPITCH + ko + lc + 4];
                    #pragma unroll
                    for (int mt = 0; mt < 2; ++mt) {
                        mmab(acc[mt][g], qa[mt][0].x, qa[mt][1].x, qa[mt][2].x, qa[mt][3].x,
                             p0.x, p1.x);
                        mmab(acc[mt][g], qa[mt][0].x, qa[mt][1].x, qa[mt][2].x, qa[mt][3].x,
                             p0.y, p1.y);
                        mmab(acc[mt][g], qa[mt][0].y, qa[mt][1].y, qa[mt][2].y, qa[mt][3].y,
                             p0.x, p1.x);
                    }
                }
            }
            __syncthreads();   // buffer b free for the issue at iteration c+1
        }

        // ---- GRU epilogue ----
        #pragma unroll
        for (int mt = 0; mt < 2; ++mt) {
            #pragma unroll
            for (int half = 0; half < 2; ++half) {
                int m = m0 + wm * 32 + mt * 16 + lr + half * 8;
                int j = j0 + jb * 8 + 2 * lc;
                float2 br = *reinterpret_cast<const float2*>(&bias[j]);
                float2 bz = *reinterpret_cast<const float2*>(&bias[HH + j]);
                float2 bi = *reinterpret_cast<const float2*>(&bias[2 * HH + j]);
                float2 bh = *reinterpret_cast<const float2*>(&bias[3 * HH + j]);
                float2 hp = *reinterpret_cast<const float2*>(&hin[(size_t)m * HH + j]);
                int i0 = half * 2, i1 = half * 2 + 1;
                float r0 = sigmoidf_(acc[mt][0][i0] + br.x);
                float r1 = sigmoidf_(acc[mt][0][i1] + br.y);
                float z0 = sigmoidf_(acc[mt][1][i0] + bz.x);
                float z1 = sigmoidf_(acc[mt][1][i1] + bz.y);
                float n0 = tanhf(acc[mt][2][i0] + bi.x + r0 * (acc[mt][3][i0] + bh.x));
                float n1 = tanhf(acc[mt][2][i1] + bi.y + r1 * (acc[mt][3][i1] + bh.y));
                float2 o;
                o.x = (1.0f - z0) * n0 + z0 * hp.x;
                o.y = (1.0f - z1) * n1 + z1 * hp.y;
                *reinterpret_cast<float2*>(&hout[(size_t)m * HH + j]) = o;
                hs_out[(size_t)m * (HH / 2) + (j >> 1)] = split2(o.x, o.y);
            }
        }

        // ---- grid barrier (monotone counter; all 128 CTAs resident) ----
        __threadfence();
        __syncthreads();
        if (tid == 0) {
            atomicAdd(&g_bar, 1u);
            unsigned target = (unsigned)NCTA * (unsigned)(s + 1);
            while (atomicAdd(&g_bar, 0u) < target) {}
        }
        __syncthreads();
        __threadfence();
    }
}

// ---------------- final projection (SIMT, one launch) ----------------
#define PBK 32
__global__ __launch_bounds__(256) void k_proj(float* __restrict__ out, int L,
                                              const float* __restrict__ Wo,
                                              const float* __restrict__ bo) {
    __shared__ float As[64][PBK + 1];
    __shared__ float Bs[64][PBK + 1];
    const int row0 = blockIdx.x * 64;
    const int tid = threadIdx.x;
    const int tx = tid & 15, ty = tid >> 4;
    float acc[4][4] = {};
    for (int k0 = 0; k0 < HH; k0 += PBK) {
        #pragma unroll
        for (int u = 0; u < 2; ++u) {
            int f = tid + u * 256; int r = f >> 3; int c = (f & 7) * 4;
            float4 v = *reinterpret_cast<const float4*>(&g_hist[(size_t)(row0 + r) * HH + k0 + c]);
            As[r][c] = v.x; As[r][c + 1] = v.y; As[r][c + 2] = v.z; As[r][c + 3] = v.w;
        }
        #pragma unroll
        for (int u = 0; u < 2; ++u) {
            int f = tid + u * 256; int r = f >> 3; int c = (f & 7) * 4;
            float4 v = *reinterpret_cast<const float4*>(&Wo[(size_t)r * HH + k0 + c]);
            Bs[r][c] = v.x; Bs[r][c + 1] = v.y; Bs[r][c + 2] = v.z; Bs[r][c + 3] = v.w;
        }
        __syncthreads();
        #pragma unroll 8
        for (int kk = 0; kk < PBK; ++kk) {
            float a[4], b[4];
            #pragma unroll
            for (int i = 0; i < 4; ++i) a[i] = As[ty + 16 * i][kk];
            #pragma unroll
            for (int jn = 0; jn < 4; ++jn) b[jn] = Bs[tx + 16 * jn][kk];
            #pragma unroll
            for (int i = 0; i < 4; ++i)
                #pragma unroll
                for (int jn = 0; jn < 4; ++jn) acc[i][jn] += a[i] * b[jn];
        }
        __syncthreads();
    }
    #pragma unroll
    for (int i = 0; i < 4; ++i) {
        int row = row0 + ty + 16 * i;
        int tt = row >> 9;
        int b = row & (BB - 1);
        #pragma unroll
        for (int jn = 0; jn < 4; ++jn) {
            int o = tx + 16 * jn;
            out[((size_t)b * L + tt) * OO + o] = acc[i][jn] + bo[o];
        }
    }
}

// ---------------- host launcher ----------------
extern "C" void kernel_launch(void* const* d_in, const int* in_sizes, int n_in,
                              void* d_out, int out_size) {
    (void)n_in; (void)in_sizes;
    const float* input = (const float*)d_in[0];
    const float* Wih   = (const float*)d_in[1];
    const float* Whh   = (const float*)d_in[2];
    const float* bih   = (const float*)d_in[3];
    const float* bhh   = (const float*)d_in[4];
    const float* Wo    = (const float*)d_in[5];
    const float* bo    = (const float*)d_in[6];
    float* out = (float*)d_out;

    int L = out_size / (BB * OO);
    if (L > LMAX) L = LMAX;
    if (L < 1) L = 1;

    cudaFuncSetAttribute(k_gru, cudaFuncAttributeMaxDynamicSharedMemorySize, SMEM_BYTES);

    k_zero_h0<<<(BB * HH + 255) / 256, 256>>>();
    k_prep_dec<<<(4 * HH * (KDEC / 2) + 255) / 256, 256>>>(Whh, Wih, Wo);
    k_prep_enc<<<(4 * HH * (KENC / 2) + 255) / 256, 256>>>(Whh, Wih);
    k_prep_x<<<(int)(((size_t)BB * TT * II / 2 + 255) / 256), 256>>>(input);
    k_prep_bias<<<(4 * HH + 255) / 256, 256>>>(bih, bhh, Wih, bo);

    dim3 grid(BB / 64, HH / 32);   // (8, 16) = 128 CTAs, all resident
    k_gru<<<grid, STEP_THREADS, SMEM_BYTES>>>(L);

    k_proj<<<L * (BB / 64), 256>>>(out, L, Wo, bo);
}

// round 15
// speedup vs baseline: 2.4158x; 1.0469x over previous
#include <cuda_runtime.h>
#include <cstdint>
#include <cstddef>

// ---------------- problem constants ----------------
#define BB 512
#define TT 128
#define II 64
#define HH 512
#define OO 64
#define LMAX 300
#define KENC 576   // [h(512) | x(64)]
#define KDEC 512

#define NCTA 128   // persistent grid size (8 x 16)

// ---------------- device scratch ----------------
__device__ float g_h[2][BB * HH];                   // fp32 encoder ping-pong
__device__ float g_hist[(size_t)LMAX * BB * HH];    // fp32 decoder hidden history
__device__ uint2 g_hs0[BB * HH / 2];                // split-h ping-pong (bf16 hi|lo pairs)
__device__ uint2 g_hs1[BB * HH / 2];
__device__ uint2 g_Wdec_s[4 * HH * KDEC / 2];
__device__ uint2 g_Wenc_s[4 * HH * KENC / 2];
__device__ uint2 g_xs[(size_t)BB * TT * II / 2];
__device__ float g_bdec[4 * HH];
__device__ float g_benc[4 * HH];
__device__ unsigned g_bar;                          // grid barrier (zeroed every launch)

// ---------------- helpers ----------------
__device__ __forceinline__ float sigmoidf_(float x) { return 1.0f / (1.0f + __expf(-x)); }

__device__ __forceinline__ uint2 split2(float v0, float v1) {
    uint32_t hi;
    asm("cvt.rn.bf16x2.f32 %0, %1, %2;" : "=r"(hi) : "f"(v1), "f"(v0));
    float h0 = __uint_as_float(hi << 16);
    float h1 = __uint_as_float(hi & 0xFFFF0000u);
    uint32_t lo;
    asm("cvt.rn.bf16x2.f32 %0, %1, %2;" : "=r"(lo) : "f"(v1 - h1), "f"(v0 - h0));
    return make_uint2(hi, lo);
}

__device__ __forceinline__ void mmab(float d[4], uint32_t a0, uint32_t a1, uint32_t a2,
                                     uint32_t a3, uint32_t b0, uint32_t b1) {
    asm volatile(
        "mma.sync.aligned.m16n8k16.row.col.f32.bf16.bf16.f32 "
        "{%0,%1,%2,%3},{%4,%5,%6,%7},{%8,%9},{%0,%1,%2,%3};"
        : "+f"(d[0]), "+f"(d[1]), "+f"(d[2]), "+f"(d[3])
        : "r"(a0), "r"(a1), "r"(a2), "r"(a3), "r"(b0), "r"(b1));
}

__device__ __forceinline__ void cp16(uint32_t saddr, const void* gaddr) {
    asm volatile("cp.async.cg.shared.global [%0], [%1], 16;"
                 :: "r"(saddr), "l"(gaddr) : "memory");
}
__device__ __forceinline__ uint32_t smem_u32_(const void* p) {
    uint32_t a;
    asm("{ .reg .u64 t; cvta.to.shared.u64 t, %1; cvt.u32.u64 %0, t; }" : "=r"(a) : "l"(p));
    return a;
}

// ---------------- prep kernels ----------------
__global__ void k_zero_h0() {
    int i = blockIdx.x * blockDim.x + threadIdx.x;
    if (i < BB * HH) g_h[0][i] = 0.0f;
    if (i < BB * HH / 2) g_hs0[i] = make_uint2(0u, 0u);
    if (i == 0) g_bar = 0u;
}

__global__ void k_prep_dec(const float* __restrict__ Whh, const float* __restrict__ Wih,
                           const float* __restrict__ Wo) {
    int idx = blockIdx.x * blockDim.x + threadIdx.x;
    if (idx >= 4 * HH * (KDEC / 2)) return;
    int row = idx / (KDEC / 2);
    int kp = idx % (KDEC / 2);
    float v[2];
    #pragma unroll
    for (int e = 0; e < 2; ++e) {
        int k = 2 * kp + e;
        if (row < 3 * HH) {
            float s = 0.0f;
            const float* wr = Wih + (size_t)row * II;
            #pragma unroll 8
            for (int o = 0; o < II; ++o) s += wr[o] * Wo[(size_t)o * HH + k];
            v[e] = (row < 2 * HH) ? (Whh[(size_t)row * HH + k] + s) : s;
        } else {
            v[e] = Whh[(size_t)(row - HH) * HH + k];
        }
    }
    g_Wdec_s[idx] = split2(v[0], v[1]);
}

__global__ void k_prep_enc(const float* __restrict__ Whh, const float* __restrict__ Wih) {
    int idx = blockIdx.x * blockDim.x + threadIdx.x;
    if (idx >= 4 * HH * (KENC / 2)) return;
    int row = idx / (KENC / 2);
    int kp = idx % (KENC / 2);
    int g = row >> 9, j = row & (HH - 1);
    float v[2];
    #pragma unroll
    for (int e = 0; e < 2; ++e) {
        int k = 2 * kp + e;
        float val = 0.0f;
        if (g == 0) val = (k < HH) ? Whh[(size_t)j * HH + k]            : Wih[(size_t)j * II + (k - HH)];
        if (g == 1) val = (k < HH) ? Whh[(size_t)(HH + j) * HH + k]     : Wih[(size_t)(HH + j) * II + (k - HH)];
        if (g == 2) val = (k < HH) ? 0.0f                               : Wih[(size_t)(2 * HH + j) * II + (k - HH)];
        if (g == 3) val = (k < HH) ? Whh[(size_t)(2 * HH + j) * HH + k] : 0.0f;
        v[e] = val;
    }
    g_Wenc_s[idx] = split2(v[0], v[1]);
}

__global__ void k_prep_x(const float* __restrict__ input) {
    size_t idx = (size_t)blockIdx.x * blockDim.x + threadIdx.x;
    if (idx >= (size_t)BB * TT * II / 2) return;
    g_xs[idx] = split2(input[2 * idx], input[2 * idx + 1]);
}

__global__ void k_prep_bias(const float* __restrict__ bih, const float* __restrict__ bhh,
                            const float* __restrict__ Wih, const float* __restrict__ bo) {
    int idx = blockIdx.x * blockDim.x + threadIdx.x;
    if (idx >= 4 * HH) return;
    int g = idx >> 9, j = idx & (HH - 1);
    float be;
    if (g == 0) be = bih[j] + bhh[j];
    else if (g == 1) be = bih[HH + j] + bhh[HH + j];
    else if (g == 2) be = bih[2 * HH + j];
    else be = bhh[2 * HH + j];
    g_benc[idx] = be;
    float bd;
    if (g < 3) {
        int r = g * HH + j;
        float s = 0.0f;
        const float* wr = Wih + (size_t)r * II;
        #pragma unroll 8
        for (int o = 0; o < II; ++o) s += wr[o] * bo[o];
        bd = bih[r] + s + ((g < 2) ? bhh[r] : 0.0f);
    } else {
        bd = bhh[2 * HH + j];
    }
    g_bdec[idx] = bd;
}

// ---------------- persistent fused GRU ----------------
// grid (8, 16) = 128 CTAs, 1/SM. CTA tile 64 batch x (4 gates x 32 j).
// 3-stage cp.async pipeline (1 syncthreads per chunk); bf16x3 mma; register epilogue;
// release-arrive / acquire-poll grid barrier between steps.
#define STEP_THREADS 256
#define SPITCH 20                                      // u64 per smem row
#define ROWS_BUF 192                                   // 64 A rows + 128 B rows
#define BUF_U64 (ROWS_BUF * SPITCH)
#define SMEM_BYTES (3 * BUF_U64 * 8)                   // 92160

__global__ __launch_bounds__(STEP_THREADS, 1) void k_gru(int L) {
    extern __shared__ __align__(16) uint2 sm[];        // [3][192][SPITCH]

    const int tid = threadIdx.x, lane = tid & 31, wid = tid >> 5;
    const int wm = wid >> 2, jb = wid & 3;
    const int m0 = blockIdx.x * 64, j0 = blockIdx.y * 32;
    const int lr = lane >> 2, lc = lane & 3;
    const uint32_t sbase = smem_u32_(sm);

    const int arow = (tid >> 3);
    const int acp = (tid & 7) * 2;

    const int total = TT + (L - 1);
    for (int s = 0; s < total; ++s) {
        const int mode = (s < TT) ? 0 : 1;
        const int t = mode ? (s - TT) : s;

        const float* hin;
        float* hout;
        const uint2* hs_in;
        uint2* hs_out;
        const uint2* Ws;
        const float* bias;
        int Kdim;
        if (mode == 0) {
            hin = g_h[t & 1];
            hout = (t == TT - 1) ? g_hist : g_h[(t + 1) & 1];
            hs_in = (t & 1) ? g_hs1 : g_hs0;
            hs_out = (t & 1) ? g_hs0 : g_hs1;
            Ws = g_Wenc_s; bias = g_benc; Kdim = KENC;
        } else {
            hin = g_hist + (size_t)t * BB * HH;
            hout = g_hist + (size_t)(t + 1) * BB * HH;
            hs_in = (t & 1) ? g_hs1 : g_hs0;
            hs_out = (t & 1) ? g_hs0 : g_hs1;
            Ws = g_Wdec_s; bias = g_bdec; Kdim = KDEC;
        }
        const int NC = Kdim / 32;

        float acc[2][4][4];
        #pragma unroll
        for (int a = 0; a < 2; ++a)
            #pragma unroll
            for (int b = 0; b < 4; ++b)
                #pragma unroll
                for (int q = 0; q < 4; ++q) acc[a][b][q] = 0.0f;

        // ---- issue chunk cc into buffer cc%3 (no-op past the end) ----
        auto issue = [&](int cc) {
            if (cc >= NC) { asm volatile("cp.async.commit_group;" ::: "memory"); return; }
            const int kp0 = cc * 16;
            const uint32_t bb_ = sbase + (uint32_t)(cc % 3) * (BUF_U64 * 8);
            #pragma unroll
            for (int u = 0; u < 2; ++u) {
                int r = arow + u * 32;
                const void* gp = (kp0 < HH / 2)
                    ? (const void*)&hs_in[(size_t)(m0 + r) * (HH / 2) + kp0 + acp]
                    : (const void*)&g_xs[(size_t)(m0 + r) * (TT * II / 2) + (size_t)t * (II / 2) + (kp0 - HH / 2) + acp];
                cp16(bb_ + (uint32_t)(r * SPITCH + acp) * 8, gp);
            }
            #pragma unroll
            for (int u = 0; u < 4; ++u) {
                int f = tid + u * 256;
                int n = f >> 3, cp = (f & 7) * 2;
                size_t row = (size_t)((n >> 5) * HH + j0 + (n & 31));
                cp16(bb_ + (uint32_t)((64 + n) * SPITCH + cp) * 8,
                     &Ws[row * (Kdim / 2) + kp0 + cp]);
            }
            asm volatile("cp.async.commit_group;" ::: "memory");
        };

        issue(0);
        issue(1);
        for (int c = 0; c < NC; ++c) {
            // group c must be complete; at most one (c+1) may still be in flight
            if (c + 1 < NC) {
                asm volatile("cp.async.wait_group 1;" ::: "memory");
            } else {
                asm volatile("cp.async.wait_group 0;" ::: "memory");
            }
            __syncthreads();   // also guarantees compute(c-1) finished CTA-wide

            const uint2* A = sm + (size_t)(c % 3) * BUF_U64;      // rows 0..63
            const uint2* Bm = A + 64 * SPITCH;                    // rows 0..127
            #pragma unroll
            for (int ks = 0; ks < 2; ++ks) {
                const int ko = ks * 8;
                uint2 qa[2][4];
                #pragma unroll
                for (int mt = 0; mt < 2; ++mt) {
                    int ar = wm * 32 + mt * 16 + lr;
                    qa[mt][0] = A[ar * SPITCH + ko + lc];
                    qa[mt][1] = A[(ar + 8) * SPITCH + ko + lc];
                    qa[mt][2] = A[ar * SPITCH + ko + lc + 4];
                    qa[mt][3] = A[(ar + 8) * SPITCH + ko + lc + 4];
                }
                #pragma unroll
                for (int g = 0; g < 4; ++g) {
                    int bn = g * 32 + jb * 8 + lr;
                    uint2 p0 = Bm[bn * SPITCH + ko + lc];
                    uint2 p1 = Bm[bn * SPITCH + ko + lc + 4];
                    #pragma unroll
                    for (int mt = 0; mt < 2; ++mt) {
                        mmab(acc[mt][g], qa[mt][0].x, qa[mt][1].x, qa[mt][2].x, qa[mt][3].x,
                             p0.x, p1.x);
                        mmab(acc[mt][g], qa[mt][0].x, qa[mt][1].x, qa[mt][2].x, qa[mt][3].x,
                             p0.y, p1.y);
                        mmab(acc[mt][g], qa[mt][0].y, qa[mt][1].y, qa[mt][2].y, qa[mt][3].y,
                             p0.x, p1.x);
                    }
                }
            }
            issue(c + 2);   // safe: buf (c+2)%3 == (c-1)%3, compute(c-1) done since the sync above
        }

        // ---- GRU epilogue ----
        #pragma unroll
        for (int mt = 0; mt < 2; ++mt) {
            #pragma unroll
            for (int half = 0; half < 2; ++half) {
                int m = m0 + wm * 32 + mt * 16 + lr + half * 8;
                int j = j0 + jb * 8 + 2 * lc;
                float2 br = *reinterpret_cast<const float2*>(&bias[j]);
                float2 bz = *reinterpret_cast<const float2*>(&bias[HH + j]);
                float2 bi = *reinterpret_cast<const float2*>(&bias[2 * HH + j]);
                float2 bh = *reinterpret_cast<const float2*>(&bias[3 * HH + j]);
                float2 hp = *reinterpret_cast<const float2*>(&hin[(size_t)m * HH + j]);
                int i0 = half * 2, i1 = half * 2 + 1;
                float r0 = sigmoidf_(acc[mt][0][i0] + br.x);
                float r1 = sigmoidf_(acc[mt][0][i1] + br.y);
                float z0 = sigmoidf_(acc[mt][1][i0] + bz.x);
                float z1 = sigmoidf_(acc[mt][1][i1] + bz.y);
                float n0 = tanhf(acc[mt][2][i0] + bi.x + r0 * (acc[mt][3][i0] + bh.x));
                float n1 = tanhf(acc[mt][2][i1] + bi.y + r1 * (acc[mt][3][i1] + bh.y));
                float2 o;
                o.x = (1.0f - z0) * n0 + z0 * hp.x;
                o.y = (1.0f - z1) * n1 + z1 * hp.y;
                *reinterpret_cast<float2*>(&hout[(size_t)m * HH + j]) = o;
                hs_out[(size_t)m * (HH / 2) + (j >> 1)] = split2(o.x, o.y);
            }
        }

        // ---- grid barrier: release arrive + acquire poll ----
        __threadfence();
        __syncthreads();
        if (tid == 0) {
            atomicAdd(&g_bar, 1u);
            const unsigned target = (unsigned)NCTA * (unsigned)(s + 1);
            unsigned v;
            do {
                asm volatile("ld.acquire.gpu.global.u32 %0, [%1];"
                             : "=r"(v) : "l"(&g_bar) : "memory");
                if (v < target) __nanosleep(64);
            } while (v < target);
        }
        __syncthreads();
    }
}

// ---------------- final projection (SIMT, one launch) ----------------
#define PBK 32
__global__ __launch_bounds__(256) void k_proj(float* __restrict__ out, int L,
                                              const float* __restrict__ Wo,
                                              const float* __restrict__ bo) {
    __shared__ float As[64][PBK + 1];
    __shared__ float Bs[64][PBK + 1];
    const int row0 = blockIdx.x * 64;
    const int tid = threadIdx.x;
    const int tx = tid & 15, ty = tid >> 4;
    float acc[4][4] = {};
    for (int k0 = 0; k0 < HH; k0 += PBK) {
        #pragma unroll
        for (int u = 0; u < 2; ++u) {
            int f = tid + u * 256; int r = f >> 3; int c = (f & 7) * 4;
            float4 v = *reinterpret_cast<const float4*>(&g_hist[(size_t)(row0 + r) * HH + k0 + c]);
            As[r][c] = v.x; As[r][c + 1] = v.y; As[r][c + 2] = v.z; As[r][c + 3] = v.w;
        }
        #pragma unroll
        for (int u = 0; u < 2; ++u) {
            int f = tid + u * 256; int r = f >> 3; int c = (f & 7) * 4;
            float4 v = *reinterpret_cast<const float4*>(&Wo[(size_t)r * HH + k0 + c]);
            Bs[r][c] = v.x; Bs[r][c + 1] = v.y; Bs[r][c + 2] = v.z; Bs[r][c + 3] = v.w;
        }
        __syncthreads();
        #pragma unroll 8
        for (int kk = 0; kk < PBK; ++kk) {
            float a[4], b[4];
            #pragma unroll
            for (int i = 0; i < 4; ++i) a[i] = As[ty + 16 * i][kk];
            #pragma unroll
            for (int jn = 0; jn < 4; ++jn) b[jn] = Bs[tx + 16 * jn][kk];
            #pragma unroll
            for (int i = 0; i < 4; ++i)
                #pragma unroll
                for (int jn = 0; jn < 4; ++jn) acc[i][jn] += a[i] * b[jn];
        }
        __syncthreads();
    }
    #pragma unroll
    for (int i = 0; i < 4; ++i) {
        int row = row0 + ty + 16 * i;
        int tt = row >> 9;
        int b = row & (BB - 1);
        #pragma unroll
        for (int jn = 0; jn < 4; ++jn) {
            int o = tx + 16 * jn;
            out[((size_t)b * L + tt) * OO + o] = acc[i][jn] + bo[o];
        }
    }
}

// ---------------- host launcher ----------------
extern "C" void kernel_launch(void* const* d_in, const int* in_sizes, int n_in,
                              void* d_out, int out_size) {
    (void)n_in; (void)in_sizes;
    const float* input = (const float*)d_in[0];
    const float* Wih   = (const float*)d_in[1];
    const float* Whh   = (const float*)d_in[2];
    const float* bih   = (const float*)d_in[3];
    const float* bhh   = (const float*)d_in[4];
    const float* Wo    = (const float*)d_in[5];
    const float* bo    = (const float*)d_in[6];
    float* out = (float*)d_out;

    int L = out_size / (BB * OO);
    if (L > LMAX) L = LMAX;
    if (L < 1) L = 1;

    cudaFuncSetAttribute(k_gru, cudaFuncAttributeMaxDynamicSharedMemorySize, SMEM_BYTES);

    k_zero_h0<<<(BB * HH + 255) / 256, 256>>>();
    k_prep_dec<<<(4 * HH * (KDEC / 2) + 255) / 256, 256>>>(Whh, Wih, Wo);
    k_prep_enc<<<(4 * HH * (KENC / 2) + 255) / 256, 256>>>(Whh, Wih);
    k_prep_x<<<(int)(((size_t)BB * TT * II / 2 + 255) / 256), 256>>>(input);
    k_prep_bias<<<(4 * HH + 255) / 256, 256>>>(bih, bhh, Wih, bo);

    dim3 grid(BB / 64, HH / 32);   // (8, 16) = 128 CTAs, all resident
    k_gru<<<grid, STEP_THREADS, SMEM_BYTES>>>(L);

    k_proj<<<L * (BB / 64), 256>>>(out, L, Wo, bo);
}